// round 8
// baseline (speedup 1.0000x reference)
#include <cuda_runtime.h>
#include <cuda_bf16.h>
#include <cstdint>

// BasicEdgeModel restructured:
//   Pa = x @ W1[0:64], Pb = x @ W1[64:128]  (precomputed per launch)
//   h  = relu(Pa[src] + Pb[tgt] + ea @ W1[128:160] + b1)
//   out= h @ W2 + b2
// Round 6: TILE_E=64, wide register tiles + LDS.128 so L1 wavefronts per ffma2
// drop below the 0.5 fma-bound threshold. Target: fma-pipe saturation (~620us).

#define E_TOTAL   1600000
#define N_NODES   100000
#define NODE_DIM  64
#define EDGE_DIM  32
#define HID       128
#define OUTD      64
#define TILE_E    64
#define ESTRIDE   68     // shared row stride (floats): 272B, 16B-aligned, bank-shift 4

typedef unsigned long long ull;

__device__ float g_Pa[(size_t)N_NODES * HID];   // 51.2 MB
__device__ float g_Pb[(size_t)N_NODES * HID];   // 51.2 MB

__device__ __forceinline__ ull pack2(float x) {
    ull r; asm("mov.b64 %0, {%1, %1};" : "=l"(r) : "f"(x)); return r;
}
__device__ __forceinline__ ull pack2f(float lo, float hi) {
    ull r; asm("mov.b64 %0, {%1, %2};" : "=l"(r) : "f"(lo), "f"(hi)); return r;
}
__device__ __forceinline__ ull ffma2(ull a, ull b, ull c) {
    ull d; asm("fma.rn.f32x2 %0, %1, %2, %3;" : "=l"(d) : "l"(a), "l"(b), "l"(c)); return d;
}
__device__ __forceinline__ void unpack2(ull v, float& lo, float& hi) {
    asm("mov.b64 {%0, %1}, %2;" : "=f"(lo), "=f"(hi) : "l"(v));
}

// ---------------------------------------------------------------------------
// Prep: Pa[n][j] = sum_{k<64} x[n][k]*W1[k][j],  Pb with W1[64+k][j]
// ---------------------------------------------------------------------------
__global__ void __launch_bounds__(128)
prep_nodes_kernel(const float* __restrict__ x, const float* __restrict__ W1)
{
    __shared__ float xs[NODE_DIM * 18];
    const int t  = threadIdx.x;
    const int nb = blockIdx.x * 16;

    #pragma unroll
    for (int r = 0; r < 2; r++) {
        int u = t + r * 128;
        int n  = u >> 4;
        int kc = u & 15;
        float4 v = *(const float4*)(x + (size_t)(nb + n) * NODE_DIM + kc * 4);
        xs[(kc * 4 + 0) * 18 + n] = v.x;
        xs[(kc * 4 + 1) * 18 + n] = v.y;
        xs[(kc * 4 + 2) * 18 + n] = v.z;
        xs[(kc * 4 + 3) * 18 + n] = v.w;
    }
    __syncthreads();

    ull accA[8], accB[8];
    #pragma unroll
    for (int u = 0; u < 8; u++) { accA[u] = 0ULL; accB[u] = 0ULL; }

    #pragma unroll 4
    for (int k = 0; k < 64; k++) {
        const ull wa = pack2(W1[k * HID + t]);
        const ull wb = pack2(W1[(64 + k) * HID + t]);
        const ull* m = (const ull*)&xs[k * 18];
        #pragma unroll
        for (int u = 0; u < 8; u++) {
            accA[u] = ffma2(m[u], wa, accA[u]);
            accB[u] = ffma2(m[u], wb, accB[u]);
        }
    }

    #pragma unroll
    for (int u = 0; u < 8; u++) {
        float lo, hi;
        unpack2(accA[u], lo, hi);
        g_Pa[(size_t)(nb + 2 * u) * HID + t]     = lo;
        g_Pa[(size_t)(nb + 2 * u + 1) * HID + t] = hi;
        unpack2(accB[u], lo, hi);
        g_Pb[(size_t)(nb + 2 * u) * HID + t]     = lo;
        g_Pb[(size_t)(nb + 2 * u + 1) * HID + t] = hi;
    }
}

// ---------------------------------------------------------------------------
// Main: 64 edges per 128-thread block.
// Phase B:  thread = 4 j-cols (j0=4*(t>>2)) x 16 edges (eg=t&3)
// GEMM2:    thread = 4 n-cols (n0=4*(t&15)) x 8 edges (eg2=t>>4)
// ---------------------------------------------------------------------------
__global__ void __launch_bounds__(128, 4)
edge_main_kernel(const float* __restrict__ ea,
                 const float* __restrict__ W1,
                 const float* __restrict__ b1,
                 const float* __restrict__ W2,
                 const float* __restrict__ b2,
                 const int* __restrict__ eidx,
                 float* __restrict__ out)
{
    __shared__ __align__(16) float eat[EDGE_DIM * ESTRIDE];   // [k][e]
    __shared__ __align__(16) float hbuf[HID * ESTRIDE];       // [j][e]
    __shared__ int sidx[TILE_E];
    __shared__ int tidx[TILE_E];

    const int t = threadIdx.x;
    const long long ebase = (long long)blockIdx.x * TILE_E;

    // indices (int32, [2, E] row-major): 128 threads load 2*64 values
    {
        int e   = t & 63;
        int row = t >> 6;
        int v = eidx[(long long)row * E_TOTAL + ebase + e];
        if (row == 0) sidx[e] = v; else tidx[e] = v;
    }

    // stage ea transposed: eat[k][e]  (64 edges x 32 floats = 512 float4)
    #pragma unroll
    for (int r = 0; r < 4; r++) {
        int u  = t + r * 128;    // 0..511
        int e  = u >> 3;         // 0..63
        int kc = u & 7;
        float4 v = *(const float4*)(ea + (ebase + e) * EDGE_DIM + kc * 4);
        eat[(kc * 4 + 0) * ESTRIDE + e] = v.x;
        eat[(kc * 4 + 1) * ESTRIDE + e] = v.y;
        eat[(kc * 4 + 2) * ESTRIDE + e] = v.z;
        eat[(kc * 4 + 3) * ESTRIDE + e] = v.w;
    }
    __syncthreads();

    // ---- phase B: acc[i][p] = (ea @ W1c) for 4 j-cols x 8 edge-pairs ----
    const int jg = t >> 2;           // 0..31
    const int eg = t & 3;            // 0..3
    const int j0 = jg * 4;
    const int e0 = eg * 16;

    ull acc[4][8];
    #pragma unroll
    for (int i = 0; i < 4; i++)
        #pragma unroll
        for (int p = 0; p < 8; p++) acc[i][p] = 0ULL;

    const float* w1c = W1 + 128 * HID + j0;
    #pragma unroll 2
    for (int k = 0; k < EDGE_DIM; k++) {
        const float4 w = *(const float4*)(w1c + k * HID);          // L1-hit LDG.128
        const float4* ms = (const float4*)&eat[k * ESTRIDE + e0];  // 4x LDS.128
        float4 m4[4];
        #pragma unroll
        for (int q = 0; q < 4; q++) m4[q] = ms[q];
        const ull* mp = (const ull*)m4;                            // 8 edge pairs
        const ull w0 = pack2(w.x), w1 = pack2(w.y), w2 = pack2(w.z), w3 = pack2(w.w);
        #pragma unroll
        for (int p = 0; p < 8; p++) {
            acc[0][p] = ffma2(mp[p], w0, acc[0][p]);
            acc[1][p] = ffma2(mp[p], w1, acc[1][p]);
            acc[2][p] = ffma2(mp[p], w2, acc[2][p]);
            acc[3][p] = ffma2(mp[p], w3, acc[3][p]);
        }
    }

    // ---- epilogue: + Pa[src] + Pb[tgt] + b1, relu -> hbuf ----
    {
        const float4 b1v = *(const float4*)(b1 + j0);
        const float* b1s = (const float*)&b1v;
        #pragma unroll
        for (int p = 0; p < 8; p++) {
            const int el = e0 + 2 * p;
            const float4 a0 = *(const float4*)(g_Pa + (size_t)sidx[el] * HID + j0);
            const float4 c0 = *(const float4*)(g_Pb + (size_t)tidx[el] * HID + j0);
            const float4 a1 = *(const float4*)(g_Pa + (size_t)sidx[el + 1] * HID + j0);
            const float4 c1 = *(const float4*)(g_Pb + (size_t)tidx[el + 1] * HID + j0);
            const float* a0s = (const float*)&a0; const float* c0s = (const float*)&c0;
            const float* a1s = (const float*)&a1; const float* c1s = (const float*)&c1;
            #pragma unroll
            for (int i = 0; i < 4; i++) {
                float lo, hi;
                unpack2(acc[i][p], lo, hi);
                lo = fmaxf(lo + a0s[i] + c0s[i] + b1s[i], 0.0f);
                hi = fmaxf(hi + a1s[i] + c1s[i] + b1s[i], 0.0f);
                *(ull*)&hbuf[(j0 + i) * ESTRIDE + el] = pack2f(lo, hi);
            }
        }
    }
    __syncthreads();

    // ---- GEMM2: out[e][n] = b2[n] + sum_j hbuf[j][e] * W2[j][n] ----
    {
        const int ng  = t & 15;
        const int eg2 = t >> 4;      // 0..7
        const int n0  = ng * 4;
        const int ee0 = eg2 * 8;

        ull acc2[4][4];
        {
            const float4 b2v = *(const float4*)(b2 + n0);
            const float* b2s = (const float*)&b2v;
            #pragma unroll
            for (int i = 0; i < 4; i++) {
                const ull bi = pack2(b2s[i]);
                #pragma unroll
                for (int p = 0; p < 4; p++) acc2[i][p] = bi;
            }
        }

        const float* w2p = W2 + n0;
        #pragma unroll 4
        for (int j = 0; j < HID; j++) {
            const float4 w = *(const float4*)(w2p + j * OUTD);         // L1-hit LDG.128
            const float4* ms = (const float4*)&hbuf[j * ESTRIDE + ee0]; // 2x LDS.128
            float4 m4[2];
            m4[0] = ms[0]; m4[1] = ms[1];
            const ull* mp = (const ull*)m4;                             // 4 edge pairs
            const ull w0 = pack2(w.x), w1 = pack2(w.y), w2_ = pack2(w.z), w3 = pack2(w.w);
            #pragma unroll
            for (int p = 0; p < 4; p++) {
                acc2[0][p] = ffma2(mp[p], w0, acc2[0][p]);
                acc2[1][p] = ffma2(mp[p], w1, acc2[1][p]);
                acc2[2][p] = ffma2(mp[p], w2_, acc2[2][p]);
                acc2[3][p] = ffma2(mp[p], w3, acc2[3][p]);
            }
        }

        #pragma unroll
        for (int p = 0; p < 4; p++) {
            float lo0, hi0, lo1, hi1, lo2, hi2, lo3, hi3;
            unpack2(acc2[0][p], lo0, hi0);
            unpack2(acc2[1][p], lo1, hi1);
            unpack2(acc2[2][p], lo2, hi2);
            unpack2(acc2[3][p], lo3, hi3);
            float4 v0 = make_float4(lo0, lo1, lo2, lo3);
            float4 v1 = make_float4(hi0, hi1, hi2, hi3);
            *(float4*)(out + (ebase + ee0 + 2 * p) * OUTD + n0)     = v0;
            *(float4*)(out + (ebase + ee0 + 2 * p + 1) * OUTD + n0) = v1;
        }
    }
}

extern "C" void kernel_launch(void* const* d_in, const int* in_sizes, int n_in,
                              void* d_out, int out_size) {
    const float* x   = (const float*)d_in[0];
    const float* ea  = (const float*)d_in[1];
    const float* W1  = (const float*)d_in[2];
    const float* b1  = (const float*)d_in[3];
    const float* W2  = (const float*)d_in[4];
    const float* b2  = (const float*)d_in[5];
    const int*   ei  = (const int*)d_in[6];
    float*       out = (float*)d_out;

    prep_nodes_kernel<<<N_NODES / 16, 128>>>(x, W1);                   // 6250 blocks
    edge_main_kernel<<<E_TOTAL / TILE_E, 128>>>(ea, W1, b1, W2, b2, ei, out);  // 25000 blocks
}

// round 11
// speedup vs baseline: 1.0311x; 1.0311x over previous
#include <cuda_runtime.h>
#include <cuda_bf16.h>
#include <cstdint>

// BasicEdgeModel via warp-level mma.sync bf16-split (sm_103-safe, no tcgen05).
//   merged = [x[src]|x[tgt]|ea] (K=160) -> split bf16 hi/lo
//   GEMM1: D1 = merged @ W1 (M=128 edges, N=128), 3 split passes
//   h = relu(D1+b1) -> split -> GEMM2: D2 = h @ W2 (N=64), 3 passes; out = D2+b2
// Persistent kernel: weights staged to smem once, loop over 12500 tiles.
// R10 fix: B fragment pairing for mma.m16n8k16 is {frag[nt&1], frag[(nt&1)+2]}.

#define E_TOTAL  1600000
#define TILE_E   128
#define N_TILES  (E_TOTAL / TILE_E)   // 12500
#define HID      128
#define OUTD     64
#define KP1      168    // padded K stride (bf16) for A1/B1: 336B rows, LDSM conflict-free
#define KP2      136    // padded K stride for hbuf/B2: 272B rows, conflict-free

// ---- smem layout (bytes, all 16B aligned) ----
#define OFF_A1H  0                 // 128 x KP1 bf16 = 43008
#define OFF_A1L  43008
#define OFF_B1H  86016             // W1^T [128 n][KP1 k]
#define OFF_B1L  129024
#define OFF_B2H  172032            // W2^T [64 n][KP2 k] = 17408
#define OFF_B2L  189440
#define OFF_SB1  206848            // b1: 128 f32
#define OFF_SB2  207360            // b2: 64 f32
#define SMEM_TOTAL 207616
// hbuf overlays the (dead after GEMM1) A1 region: 128 x KP2 bf16 = 34816 each
#define OFF_HBH  0
#define OFF_HBL  34816

__device__ __forceinline__ uint32_t smem_u32(const void* p) {
    uint32_t a;
    asm("{ .reg .u64 t; cvta.to.shared.u64 t, %1; cvt.u32.u64 %0, t; }" : "=r"(a) : "l"(p));
    return a;
}
// split v0,v1 into packed bf16x2 hi (leading) and lo (residual) words.
__device__ __forceinline__ void split2(float v0, float v1, uint32_t& hi, uint32_t& lo) {
    asm("cvt.rn.bf16x2.f32 %0, %1, %2;" : "=r"(hi) : "f"(v1), "f"(v0));
    float h0 = __uint_as_float(hi << 16);
    float h1 = __uint_as_float(hi & 0xFFFF0000u);
    float r0 = v0 - h0;
    float r1 = v1 - h1;
    asm("cvt.rn.bf16x2.f32 %0, %1, %2;" : "=r"(lo) : "f"(r1), "f"(r0));
}
__device__ __forceinline__ void ldsm_x4(uint32_t* r, uint32_t addr) {
    asm volatile("ldmatrix.sync.aligned.m8n8.x4.shared.b16 {%0,%1,%2,%3}, [%4];"
                 : "=r"(r[0]), "=r"(r[1]), "=r"(r[2]), "=r"(r[3]) : "r"(addr));
}
__device__ __forceinline__ void mma_bf16(float* d, const uint32_t* a,
                                         uint32_t b0, uint32_t b1) {
    asm volatile("mma.sync.aligned.m16n8k16.row.col.f32.bf16.bf16.f32 "
                 "{%0,%1,%2,%3}, {%4,%5,%6,%7}, {%8,%9}, {%0,%1,%2,%3};"
                 : "+f"(d[0]), "+f"(d[1]), "+f"(d[2]), "+f"(d[3])
                 : "r"(a[0]), "r"(a[1]), "r"(a[2]), "r"(a[3]), "r"(b0), "r"(b1));
}

__global__ void __launch_bounds__(256, 1)
edge_mma_kernel(const float* __restrict__ x,
                const float* __restrict__ ea,
                const float* __restrict__ W1,
                const float* __restrict__ b1,
                const float* __restrict__ W2,
                const float* __restrict__ b2,
                const int* __restrict__ eidx,
                float* __restrict__ out)
{
    extern __shared__ char smem[];
    const uint32_t sb = smem_u32(smem);
    const int t = threadIdx.x;
    const int lane = t & 31;
    const int w = t >> 5;

    // ================= one-time staging =================
    if (t < 128)              ((float*)(smem + OFF_SB1))[t] = b1[t];
    else if (t < 192)         ((float*)(smem + OFF_SB2))[t - 128] = b2[t - 128];

    {   // B1 = W1^T hi/lo: [j][k]
        const int j = t & 127, kh = t >> 7;
        for (int k = kh * 80; k < kh * 80 + 80; k += 2) {
            float v0 = W1[(size_t)k * HID + j];
            float v1 = W1[(size_t)(k + 1) * HID + j];
            uint32_t hi, lo; split2(v0, v1, hi, lo);
            uint32_t off = (uint32_t)(j * KP1 + k) * 2;
            *(uint32_t*)(smem + OFF_B1H + off) = hi;
            *(uint32_t*)(smem + OFF_B1L + off) = lo;
        }
    }
    {   // B2 = W2^T hi/lo: [n][j]
        const int n = t & 63, q = t >> 6;
        for (int j = q * 32; j < q * 32 + 32; j += 2) {
            float v0 = W2[(size_t)j * OUTD + n];
            float v1 = W2[(size_t)(j + 1) * OUTD + n];
            uint32_t hi, lo; split2(v0, v1, hi, lo);
            uint32_t off = (uint32_t)(n * KP2 + j) * 2;
            *(uint32_t*)(smem + OFF_B2H + off) = hi;
            *(uint32_t*)(smem + OFF_B2L + off) = lo;
        }
    }
    __syncthreads();

    // warp tiling
    const int mw = w & 3, nw = w >> 2;
    const int m0 = mw * 32;
    const int n0g1 = nw * 64;    // GEMM1: 64 n-cols
    const int n0g2 = nw * 32;    // GEMM2: 32 n-cols
    const int lr = lane & 15;            // ldmatrix row-in-16
    const int lc = (lane >> 4) * 8;      // ldmatrix k-chunk (0 or 8)
    const int cq = 2 * (lane & 3);       // frag col pair
    const int rq = lane >> 2;            // frag row

    // ================= persistent tile loop =================
    for (int tile = blockIdx.x; tile < N_TILES; tile += gridDim.x) {
        const long long ebase = (long long)tile * TILE_E;

        // ---- stage A1 = gathered merged rows, hi/lo ----
        {
            const int e = t >> 1, half = t & 1;
            const int node = eidx[(size_t)half * E_TOTAL + ebase + e];
            const float* xr = x + (size_t)node * 64;
            const uint32_t rowoff = (uint32_t)(e * KP1) * 2;
            #pragma unroll
            for (int c4 = 0; c4 < 16; c4++) {
                float4 v = ((const float4*)xr)[c4];
                const int col = half * 64 + c4 * 4;
                uint32_t h0, l0, h1, l1;
                split2(v.x, v.y, h0, l0);
                split2(v.z, v.w, h1, l1);
                const uint32_t off = rowoff + col * 2;
                *(uint2*)(smem + OFF_A1H + off) = make_uint2(h0, h1);
                *(uint2*)(smem + OFF_A1L + off) = make_uint2(l0, l1);
            }
            if (half) {
                const float* er = ea + (size_t)(ebase + e) * 32;
                #pragma unroll
                for (int c4 = 0; c4 < 8; c4++) {
                    float4 v = ((const float4*)er)[c4];
                    const int col = 128 + c4 * 4;
                    uint32_t h0, l0, h1, l1;
                    split2(v.x, v.y, h0, l0);
                    split2(v.z, v.w, h1, l1);
                    const uint32_t off = rowoff + col * 2;
                    *(uint2*)(smem + OFF_A1H + off) = make_uint2(h0, h1);
                    *(uint2*)(smem + OFF_A1L + off) = make_uint2(l0, l1);
                }
            }
        }
        __syncthreads();

        // ---- GEMM1: acc[2][8][4] = A1 @ B1^T (3 split passes, K=160) ----
        float acc[2][8][4];
        #pragma unroll
        for (int i = 0; i < 2; i++)
            #pragma unroll
            for (int j = 0; j < 8; j++)
                #pragma unroll
                for (int q2 = 0; q2 < 4; q2++) acc[i][j][q2] = 0.0f;

        #pragma unroll 1
        for (int s = 0; s < 3; s++) {
            const uint32_t abase = sb + (s == 2 ? OFF_A1L : OFF_A1H);
            const uint32_t bbase = sb + (s == 1 ? OFF_B1L : OFF_B1H);
            const uint32_t aaddr0 = abase + ((m0 + lr) * KP1 + lc) * 2;
            const uint32_t aaddr1 = abase + ((m0 + 16 + lr) * KP1 + lc) * 2;
            uint32_t baddr[4];
            #pragma unroll
            for (int nt2 = 0; nt2 < 4; nt2++)
                baddr[nt2] = bbase + ((n0g1 + nt2 * 16 + lr) * KP1 + lc) * 2;

            #pragma unroll
            for (int ks = 0; ks < 10; ks++) {
                uint32_t a0[4], a1[4], bf[4][4];
                ldsm_x4(a0, aaddr0 + ks * 32);
                ldsm_x4(a1, aaddr1 + ks * 32);
                #pragma unroll
                for (int nt2 = 0; nt2 < 4; nt2++) ldsm_x4(bf[nt2], baddr[nt2] + ks * 32);
                #pragma unroll
                for (int nt = 0; nt < 8; nt++) {
                    // ldmatrix frag order: {n0-7/k0-7, n8-15/k0-7, n0-7/k8-15, n8-15/k8-15}
                    // mma B operand for n-block (nt&1): b0 = k0-7, b1 = k8-15 of SAME n rows
                    const uint32_t b0 = bf[nt >> 1][nt & 1];
                    const uint32_t b1v = bf[nt >> 1][(nt & 1) + 2];
                    mma_bf16(acc[0][nt], a0, b0, b1v);
                    mma_bf16(acc[1][nt], a1, b0, b1v);
                }
            }
        }
        __syncthreads();   // everyone done reading A1 before hbuf overlays it

        // ---- epilogue 1: h = relu(acc + b1) -> hbuf hi/lo ----
        {
            const float* sb1 = (const float*)(smem + OFF_SB1);
            #pragma unroll
            for (int mt = 0; mt < 2; mt++) {
                #pragma unroll
                for (int nt = 0; nt < 8; nt++) {
                    const int col = n0g1 + nt * 8 + cq;
                    const float2 bb = *(const float2*)(sb1 + col);
                    const int r0 = m0 + mt * 16 + rq;
                    float v0 = fmaxf(acc[mt][nt][0] + bb.x, 0.0f);
                    float v1 = fmaxf(acc[mt][nt][1] + bb.y, 0.0f);
                    uint32_t hi, lo; split2(v0, v1, hi, lo);
                    uint32_t off = (uint32_t)(r0 * KP2 + col) * 2;
                    *(uint32_t*)(smem + OFF_HBH + off) = hi;
                    *(uint32_t*)(smem + OFF_HBL + off) = lo;
                    v0 = fmaxf(acc[mt][nt][2] + bb.x, 0.0f);
                    v1 = fmaxf(acc[mt][nt][3] + bb.y, 0.0f);
                    split2(v0, v1, hi, lo);
                    off = (uint32_t)((r0 + 8) * KP2 + col) * 2;
                    *(uint32_t*)(smem + OFF_HBH + off) = hi;
                    *(uint32_t*)(smem + OFF_HBL + off) = lo;
                }
            }
        }
        __syncthreads();

        // ---- GEMM2: acc2[2][4][4] = hbuf @ B2^T (3 passes, K=128) ----
        float acc2[2][4][4];
        #pragma unroll
        for (int i = 0; i < 2; i++)
            #pragma unroll
            for (int j = 0; j < 4; j++)
                #pragma unroll
                for (int q2 = 0; q2 < 4; q2++) acc2[i][j][q2] = 0.0f;

        #pragma unroll 1
        for (int s = 0; s < 3; s++) {
            const uint32_t abase = sb + (s == 2 ? OFF_HBL : OFF_HBH);
            const uint32_t bbase = sb + (s == 1 ? OFF_B2L : OFF_B2H);
            const uint32_t aaddr0 = abase + ((m0 + lr) * KP2 + lc) * 2;
            const uint32_t aaddr1 = abase + ((m0 + 16 + lr) * KP2 + lc) * 2;
            const uint32_t baddr0 = bbase + ((n0g2 + lr) * KP2 + lc) * 2;
            const uint32_t baddr1 = bbase + ((n0g2 + 16 + lr) * KP2 + lc) * 2;

            #pragma unroll
            for (int ks = 0; ks < 8; ks++) {
                uint32_t a0[4], a1[4], bf[2][4];
                ldsm_x4(a0, aaddr0 + ks * 32);
                ldsm_x4(a1, aaddr1 + ks * 32);
                ldsm_x4(bf[0], baddr0 + ks * 32);
                ldsm_x4(bf[1], baddr1 + ks * 32);
                #pragma unroll
                for (int nt = 0; nt < 4; nt++) {
                    const uint32_t b0 = bf[nt >> 1][nt & 1];
                    const uint32_t b1v = bf[nt >> 1][(nt & 1) + 2];
                    mma_bf16(acc2[0][nt], a0, b0, b1v);
                    mma_bf16(acc2[1][nt], a1, b0, b1v);
                }
            }
        }

        // ---- epilogue 2: out = acc2 + b2, direct coalesced-sector STG.64 ----
        {
            const float* sb2 = (const float*)(smem + OFF_SB2);
            #pragma unroll
            for (int mt = 0; mt < 2; mt++) {
                #pragma unroll
                for (int nt = 0; nt < 4; nt++) {
                    const int col = n0g2 + nt * 8 + cq;
                    const float2 bb = *(const float2*)(sb2 + col);
                    const int r0 = m0 + mt * 16 + rq;
                    float2 o0 = make_float2(acc2[mt][nt][0] + bb.x, acc2[mt][nt][1] + bb.y);
                    float2 o1 = make_float2(acc2[mt][nt][2] + bb.x, acc2[mt][nt][3] + bb.y);
                    *(float2*)(out + (ebase + r0) * OUTD + col)     = o0;
                    *(float2*)(out + (ebase + r0 + 8) * OUTD + col) = o1;
                }
            }
        }
        __syncthreads();   // protect hbuf/A1 region before next tile's staging
    }
}

extern "C" void kernel_launch(void* const* d_in, const int* in_sizes, int n_in,
                              void* d_out, int out_size) {
    const float* x   = (const float*)d_in[0];
    const float* ea  = (const float*)d_in[1];
    const float* W1  = (const float*)d_in[2];
    const float* b1  = (const float*)d_in[3];
    const float* W2  = (const float*)d_in[4];
    const float* b2  = (const float*)d_in[5];
    const int*   ei  = (const int*)d_in[6];
    float*       out = (float*)d_out;

    int dev = 0, sms = 148;
    cudaGetDevice(&dev);
    cudaDeviceGetAttribute(&sms, cudaDevAttrMultiProcessorCount, dev);
    if (sms <= 0 || sms > N_TILES) sms = 148;

    cudaFuncSetAttribute(edge_mma_kernel,
                         cudaFuncAttributeMaxDynamicSharedMemorySize, SMEM_TOTAL);
    edge_mma_kernel<<<sms, 256, SMEM_TOTAL>>>(x, ea, W1, b1, W2, b2, ei, out);
}

// round 13
// speedup vs baseline: 1.5447x; 1.4981x over previous
#include <cuda_runtime.h>
#include <cuda_bf16.h>
#include <cstdint>

// BasicEdgeModel hybrid: fp32 Pa/Pb precompute + bf16-split mma.sync main kernel.
//   Pa = x @ W1[0:64], Pb = x @ W1[64:128]   (prep kernel, fp32 exact)
//   GEMM1 (tensor, K=32): T = ea @ W1c, 3 split passes
//   h = relu(T + Pa[src] + Pb[tgt] + b1)  -> split bf16 hi/lo
//   GEMM2 (tensor, K=128): out = h @ W2 + b2, 3 split passes
// Persistent main kernel: weights staged to smem once, loop over 12500 tiles.

#define E_TOTAL  1600000
#define N_NODES  100000
#define TILE_E   128
#define N_TILES  (E_TOTAL / TILE_E)   // 12500
#define HID      128
#define OUTD     64
#define KPA      40     // padded K stride (bf16) for A1/B1c (K=32): 80B rows, LDSM conflict-free
#define KP2      136    // padded K stride for hbuf/B2: 272B rows, conflict-free

// ---- smem layout (bytes, 16B aligned) ----
#define OFF_A1H  0                  // 128 x KPA bf16 = 10240
#define OFF_A1L  10240
#define OFF_B1H  20480              // W1c^T [128 n][KPA k]
#define OFF_B1L  30720
#define OFF_B2H  40960              // W2^T [64 n][KP2 k] = 17408
#define OFF_B2L  58368
#define OFF_HBH  75776              // hbuf [128][KP2] = 34816
#define OFF_HBL  110592
#define OFF_SB1  145408             // b1: 128 f32
#define OFF_SB2  145920             // b2: 64 f32
#define OFF_SIDX 146176             // 128 int
#define OFF_TIDX 146688             // 128 int
#define SMEM_TOTAL 147200

typedef unsigned long long ull;

__device__ float g_Pa[(size_t)N_NODES * HID];   // 51.2 MB
__device__ float g_Pb[(size_t)N_NODES * HID];   // 51.2 MB

__device__ __forceinline__ uint32_t smem_u32(const void* p) {
    uint32_t a;
    asm("{ .reg .u64 t; cvta.to.shared.u64 t, %1; cvt.u32.u64 %0, t; }" : "=r"(a) : "l"(p));
    return a;
}
__device__ __forceinline__ void split2(float v0, float v1, uint32_t& hi, uint32_t& lo) {
    asm("cvt.rn.bf16x2.f32 %0, %1, %2;" : "=r"(hi) : "f"(v1), "f"(v0));
    float h0 = __uint_as_float(hi << 16);
    float h1 = __uint_as_float(hi & 0xFFFF0000u);
    float r0 = v0 - h0;
    float r1 = v1 - h1;
    asm("cvt.rn.bf16x2.f32 %0, %1, %2;" : "=r"(lo) : "f"(r1), "f"(r0));
}
__device__ __forceinline__ void ldsm_x4(uint32_t* r, uint32_t addr) {
    asm volatile("ldmatrix.sync.aligned.m8n8.x4.shared.b16 {%0,%1,%2,%3}, [%4];"
                 : "=r"(r[0]), "=r"(r[1]), "=r"(r[2]), "=r"(r[3]) : "r"(addr));
}
__device__ __forceinline__ void mma_bf16(float* d, const uint32_t* a,
                                         uint32_t b0, uint32_t b1) {
    asm volatile("mma.sync.aligned.m16n8k16.row.col.f32.bf16.bf16.f32 "
                 "{%0,%1,%2,%3}, {%4,%5,%6,%7}, {%8,%9}, {%0,%1,%2,%3};"
                 : "+f"(d[0]), "+f"(d[1]), "+f"(d[2]), "+f"(d[3])
                 : "r"(a[0]), "r"(a[1]), "r"(a[2]), "r"(a[3]), "r"(b0), "r"(b1));
}
// fp32x2 helpers for prep kernel
__device__ __forceinline__ ull pack2(float x) {
    ull r; asm("mov.b64 %0, {%1, %1};" : "=l"(r) : "f"(x)); return r;
}
__device__ __forceinline__ ull ffma2(ull a, ull b, ull c) {
    ull d; asm("fma.rn.f32x2 %0, %1, %2, %3;" : "=l"(d) : "l"(a), "l"(b), "l"(c)); return d;
}
__device__ __forceinline__ void unpack2(ull v, float& lo, float& hi) {
    asm("mov.b64 {%0, %1}, %2;" : "=f"(lo), "=f"(hi) : "l"(v));
}

// ---------------------------------------------------------------------------
// Prep (validated round 5): Pa[n][j], Pb[n][j]
// ---------------------------------------------------------------------------
__global__ void __launch_bounds__(128)
prep_nodes_kernel(const float* __restrict__ x, const float* __restrict__ W1)
{
    __shared__ float xs[64 * 18];
    const int t  = threadIdx.x;
    const int nb = blockIdx.x * 16;

    #pragma unroll
    for (int r = 0; r < 2; r++) {
        int u = t + r * 128;
        int n  = u >> 4;
        int kc = u & 15;
        float4 v = *(const float4*)(x + (size_t)(nb + n) * 64 + kc * 4);
        xs[(kc * 4 + 0) * 18 + n] = v.x;
        xs[(kc * 4 + 1) * 18 + n] = v.y;
        xs[(kc * 4 + 2) * 18 + n] = v.z;
        xs[(kc * 4 + 3) * 18 + n] = v.w;
    }
    __syncthreads();

    ull accA[8], accB[8];
    #pragma unroll
    for (int u = 0; u < 8; u++) { accA[u] = 0ULL; accB[u] = 0ULL; }

    #pragma unroll 4
    for (int k = 0; k < 64; k++) {
        const ull wa = pack2(W1[k * HID + t]);
        const ull wb = pack2(W1[(64 + k) * HID + t]);
        const ull* m = (const ull*)&xs[k * 18];
        #pragma unroll
        for (int u = 0; u < 8; u++) {
            accA[u] = ffma2(m[u], wa, accA[u]);
            accB[u] = ffma2(m[u], wb, accB[u]);
        }
    }

    #pragma unroll
    for (int u = 0; u < 8; u++) {
        float lo, hi;
        unpack2(accA[u], lo, hi);
        g_Pa[(size_t)(nb + 2 * u) * HID + t]     = lo;
        g_Pa[(size_t)(nb + 2 * u + 1) * HID + t] = hi;
        unpack2(accB[u], lo, hi);
        g_Pb[(size_t)(nb + 2 * u) * HID + t]     = lo;
        g_Pb[(size_t)(nb + 2 * u + 1) * HID + t] = hi;
    }
}

// ---------------------------------------------------------------------------
// Main persistent kernel
// ---------------------------------------------------------------------------
__global__ void __launch_bounds__(256)
edge_hybrid_kernel(const float* __restrict__ ea,
                   const float* __restrict__ W1,
                   const float* __restrict__ b1,
                   const float* __restrict__ W2,
                   const float* __restrict__ b2,
                   const int* __restrict__ eidx,
                   float* __restrict__ out)
{
    extern __shared__ char smem[];
    const uint32_t sb = smem_u32(smem);
    const int t = threadIdx.x;
    const int lane = t & 31;
    const int w = t >> 5;

    // ================= one-time staging =================
    if (t < 128)        ((float*)(smem + OFF_SB1))[t] = b1[t];
    else if (t < 192)   ((float*)(smem + OFF_SB2))[t - 128] = b2[t - 128];

    {   // B1c = W1c^T hi/lo: [j=n][k], W1 rows 128..159
        const int j = t & 127, kh = t >> 7;
        for (int k = kh * 16; k < kh * 16 + 16; k += 2) {
            float v0 = W1[(size_t)(128 + k) * HID + j];
            float v1 = W1[(size_t)(129 + k) * HID + j];
            uint32_t hi, lo; split2(v0, v1, hi, lo);
            uint32_t off = (uint32_t)(j * KPA + k) * 2;
            *(uint32_t*)(smem + OFF_B1H + off) = hi;
            *(uint32_t*)(smem + OFF_B1L + off) = lo;
        }
    }
    {   // B2 = W2^T hi/lo: [n][j]
        const int n = t & 63, q = t >> 6;
        for (int j = q * 32; j < q * 32 + 32; j += 2) {
            float v0 = W2[(size_t)j * OUTD + n];
            float v1 = W2[(size_t)(j + 1) * OUTD + n];
            uint32_t hi, lo; split2(v0, v1, hi, lo);
            uint32_t off = (uint32_t)(n * KP2 + j) * 2;
            *(uint32_t*)(smem + OFF_B2H + off) = hi;
            *(uint32_t*)(smem + OFF_B2L + off) = lo;
        }
    }
    __syncthreads();

    // warp tiling
    const int mw = w & 3, nw = w >> 2;
    const int m0 = mw * 32;
    const int n0g1 = nw * 64;
    const int n0g2 = nw * 32;
    const int lr = lane & 15;
    const int lc = (lane >> 4) * 8;
    const int cq = 2 * (lane & 3);
    const int rq = lane >> 2;

    const int* sidx_s = (const int*)(smem + OFF_SIDX);
    const int* tidx_s = (const int*)(smem + OFF_TIDX);
    const float* sb1 = (const float*)(smem + OFF_SB1);
    const float* sb2 = (const float*)(smem + OFF_SB2);

    // ================= persistent tile loop =================
    for (int tile = blockIdx.x; tile < N_TILES; tile += gridDim.x) {
        const long long ebase = (long long)tile * TILE_E;

        // ---- stage indices + A1 (ea only, K=32) ----
        if (t < 128) ((int*)(smem + OFF_SIDX))[t] = eidx[ebase + t];
        else         ((int*)(smem + OFF_TIDX))[t - 128] = eidx[(size_t)E_TOTAL + ebase + (t - 128)];
        {
            const int e = t >> 1, half = t & 1;
            const float* er = ea + (size_t)(ebase + e) * 32 + half * 16;
            const uint32_t rowoff = (uint32_t)(e * KPA + half * 16) * 2;
            #pragma unroll
            for (int c4 = 0; c4 < 4; c4++) {
                float4 v = ((const float4*)er)[c4];
                uint32_t h0, l0, h1, l1;
                split2(v.x, v.y, h0, l0);
                split2(v.z, v.w, h1, l1);
                const uint32_t off = rowoff + c4 * 8;
                *(uint2*)(smem + OFF_A1H + off) = make_uint2(h0, h1);
                *(uint2*)(smem + OFF_A1L + off) = make_uint2(l0, l1);
            }
        }
        __syncthreads();

        // ---- GEMM1: acc = A1 @ B1c^T (3 split passes, K=32) ----
        float acc[2][8][4];
        #pragma unroll
        for (int i = 0; i < 2; i++)
            #pragma unroll
            for (int j = 0; j < 8; j++)
                #pragma unroll
                for (int q2 = 0; q2 < 4; q2++) acc[i][j][q2] = 0.0f;

        #pragma unroll
        for (int s = 0; s < 3; s++) {
            const uint32_t abase = sb + (s == 2 ? OFF_A1L : OFF_A1H);
            const uint32_t bbase = sb + (s == 1 ? OFF_B1L : OFF_B1H);
            const uint32_t aaddr0 = abase + ((m0 + lr) * KPA + lc) * 2;
            const uint32_t aaddr1 = abase + ((m0 + 16 + lr) * KPA + lc) * 2;
            uint32_t baddr[4];
            #pragma unroll
            for (int nt2 = 0; nt2 < 4; nt2++)
                baddr[nt2] = bbase + ((n0g1 + nt2 * 16 + lr) * KPA + lc) * 2;

            #pragma unroll
            for (int ks = 0; ks < 2; ks++) {
                uint32_t a0[4], a1[4], bf[4][4];
                ldsm_x4(a0, aaddr0 + ks * 32);
                ldsm_x4(a1, aaddr1 + ks * 32);
                #pragma unroll
                for (int nt2 = 0; nt2 < 4; nt2++) ldsm_x4(bf[nt2], baddr[nt2] + ks * 32);
                #pragma unroll
                for (int nt = 0; nt < 8; nt++) {
                    const uint32_t b0 = bf[nt >> 1][nt & 1];
                    const uint32_t b1v = bf[nt >> 1][(nt & 1) + 2];
                    mma_bf16(acc[0][nt], a0, b0, b1v);
                    mma_bf16(acc[1][nt], a1, b0, b1v);
                }
            }
        }

        // ---- epilogue 1: h = relu(acc + Pa[src] + Pb[tgt] + b1) -> hbuf ----
        #pragma unroll
        for (int mt = 0; mt < 2; mt++) {
            const int ra = m0 + mt * 16 + rq;        // rows for acc[mt][*][0..1]
            const int rb = ra + 8;                   // rows for acc[mt][*][2..3]
            const float* paA = g_Pa + (size_t)sidx_s[ra] * HID;
            const float* pbA = g_Pb + (size_t)tidx_s[ra] * HID;
            const float* paB = g_Pa + (size_t)sidx_s[rb] * HID;
            const float* pbB = g_Pb + (size_t)tidx_s[rb] * HID;
            float2 va[8], vb[8];
            #pragma unroll
            for (int nt = 0; nt < 8; nt++) {
                const int col = n0g1 + nt * 8 + cq;
                float2 p1 = *(const float2*)(paA + col);
                float2 q1 = *(const float2*)(pbA + col);
                float2 p2 = *(const float2*)(paB + col);
                float2 q2v = *(const float2*)(pbB + col);
                va[nt] = make_float2(p1.x + q1.x, p1.y + q1.y);
                vb[nt] = make_float2(p2.x + q2v.x, p2.y + q2v.y);
            }
            #pragma unroll
            for (int nt = 0; nt < 8; nt++) {
                const int col = n0g1 + nt * 8 + cq;
                const float2 bb = *(const float2*)(sb1 + col);
                float v0 = fmaxf(acc[mt][nt][0] + va[nt].x + bb.x, 0.0f);
                float v1 = fmaxf(acc[mt][nt][1] + va[nt].y + bb.y, 0.0f);
                uint32_t hi, lo; split2(v0, v1, hi, lo);
                uint32_t off = (uint32_t)(ra * KP2 + col) * 2;
                *(uint32_t*)(smem + OFF_HBH + off) = hi;
                *(uint32_t*)(smem + OFF_HBL + off) = lo;
                v0 = fmaxf(acc[mt][nt][2] + vb[nt].x + bb.x, 0.0f);
                v1 = fmaxf(acc[mt][nt][3] + vb[nt].y + bb.y, 0.0f);
                split2(v0, v1, hi, lo);
                off = (uint32_t)(rb * KP2 + col) * 2;
                *(uint32_t*)(smem + OFF_HBH + off) = hi;
                *(uint32_t*)(smem + OFF_HBL + off) = lo;
            }
        }
        __syncthreads();

        // ---- GEMM2: acc2 = hbuf @ B2^T (3 passes, K=128) ----
        float acc2[2][4][4];
        #pragma unroll
        for (int i = 0; i < 2; i++)
            #pragma unroll
            for (int j = 0; j < 4; j++)
                #pragma unroll
                for (int q2 = 0; q2 < 4; q2++) acc2[i][j][q2] = 0.0f;

        #pragma unroll 1
        for (int s = 0; s < 3; s++) {
            const uint32_t abase = sb + (s == 2 ? OFF_HBL : OFF_HBH);
            const uint32_t bbase = sb + (s == 1 ? OFF_B2L : OFF_B2H);
            const uint32_t aaddr0 = abase + ((m0 + lr) * KP2 + lc) * 2;
            const uint32_t aaddr1 = abase + ((m0 + 16 + lr) * KP2 + lc) * 2;
            const uint32_t baddr0 = bbase + ((n0g2 + lr) * KP2 + lc) * 2;
            const uint32_t baddr1 = bbase + ((n0g2 + 16 + lr) * KP2 + lc) * 2;

            #pragma unroll
            for (int ks = 0; ks < 8; ks++) {
                uint32_t a0[4], a1[4], bf[2][4];
                ldsm_x4(a0, aaddr0 + ks * 32);
                ldsm_x4(a1, aaddr1 + ks * 32);
                ldsm_x4(bf[0], baddr0 + ks * 32);
                ldsm_x4(bf[1], baddr1 + ks * 32);
                #pragma unroll
                for (int nt = 0; nt < 4; nt++) {
                    const uint32_t b0 = bf[nt >> 1][nt & 1];
                    const uint32_t b1v = bf[nt >> 1][(nt & 1) + 2];
                    mma_bf16(acc2[0][nt], a0, b0, b1v);
                    mma_bf16(acc2[1][nt], a1, b0, b1v);
                }
            }
        }

        // ---- epilogue 2: out = acc2 + b2 ----
        #pragma unroll
        for (int mt = 0; mt < 2; mt++) {
            #pragma unroll
            for (int nt = 0; nt < 4; nt++) {
                const int col = n0g2 + nt * 8 + cq;
                const float2 bb = *(const float2*)(sb2 + col);
                const int r0 = m0 + mt * 16 + rq;
                float2 o0 = make_float2(acc2[mt][nt][0] + bb.x, acc2[mt][nt][1] + bb.y);
                float2 o1 = make_float2(acc2[mt][nt][2] + bb.x, acc2[mt][nt][3] + bb.y);
                *(float2*)(out + (ebase + r0) * OUTD + col)     = o0;
                *(float2*)(out + (ebase + r0 + 8) * OUTD + col) = o1;
            }
        }
        // no end-of-loop sync needed: the post-stage sync next iteration orders
        // hbuf/A1/idx rewrites against this tile's reads.
    }
}

extern "C" void kernel_launch(void* const* d_in, const int* in_sizes, int n_in,
                              void* d_out, int out_size) {
    const float* x   = (const float*)d_in[0];
    const float* ea  = (const float*)d_in[1];
    const float* W1  = (const float*)d_in[2];
    const float* b1  = (const float*)d_in[3];
    const float* W2  = (const float*)d_in[4];
    const float* b2  = (const float*)d_in[5];
    const int*   ei  = (const int*)d_in[6];
    float*       out = (float*)d_out;

    int dev = 0, sms = 148;
    cudaGetDevice(&dev);
    cudaDeviceGetAttribute(&sms, cudaDevAttrMultiProcessorCount, dev);
    if (sms <= 0 || sms > N_TILES) sms = 148;

    prep_nodes_kernel<<<N_NODES / 16, 128>>>(x, W1);   // 6250 blocks
    cudaFuncSetAttribute(edge_hybrid_kernel,
                         cudaFuncAttributeMaxDynamicSharedMemorySize, SMEM_TOTAL);
    edge_hybrid_kernel<<<sms, 256, SMEM_TOTAL>>>(ea, W1, b1, W2, b2, ei, out);
}